// round 14
// baseline (speedup 1.0000x reference)
#include <cuda_runtime.h>
#include <cuda_bf16.h>

#define R_EARTH  6371000.0f
#define DEG2RADF 0.017453292519943295f
#define DT_SEC   600.0f
#define NSTEPS   48
#define NPAIRS   (NSTEPS / 2)

#define WOUT2 24          // output columns per warp (32 lanes - 2*4 halo)
#define SH    64          // output rows per strip
#define WPB   8           // warps per block

// Scratch ping-pong buffer (B*H*W = 8*1024*1024 floats = 32 MB) — static device
// global, NOT an allocation.
__device__ __align__(16) float g_scratch[8u * 1024u * 1024u];

__device__ float g_inv_2dx[4096];   // 0.5/dx per row; one-sided uses 2*this
__device__ float g_inv_dy;
__device__ float g_inv_2dy;

__global__ void setup_kernel(const float* __restrict__ lat,
                             const float* __restrict__ lon, int H) {
    float dlat = lat[1] - lat[0];
    float dlon = lon[1] - lon[0];
    float dy = R_EARTH * DEG2RADF * dlat;
    if (blockIdx.x == 0 && threadIdx.x == 0) {
        g_inv_dy  = 1.0f / dy;
        g_inv_2dy = 0.5f / dy;
    }
    float dx0 = R_EARTH * DEG2RADF * dlon;
    for (int i = blockIdx.x * blockDim.x + threadIdx.x; i < H;
         i += gridDim.x * blockDim.x) {
        float dx = dx0 * cosf(lat[i] * DEG2RADF);
        g_inv_2dx[i] = 0.5f / dx;
    }
}

// TWO fused timesteps per launch. Register-rolling y-sweep; per-warp strip of
// 24 output columns (lanes carry x = wc*24 + lane - 4, halo 4 each side).
// Stage 1 computes T1 = step(T) into rolling registers; stage 2, two rows
// behind, computes T2 = step(T1) and stores it. All x-neighbors via shuffles,
// all y-neighbors via rolling registers; ug/vg/mask/inv2dx pass through
// register delay lines so each global value is loaded exactly once.
__global__ __launch_bounds__(256, 2)
void step2_kernel(const float* __restrict__ src_ext, int src_is_scratch,
                  float* __restrict__ dst_ext, int dst_is_scratch,
                  const float* __restrict__ ug, const float* __restrict__ vg,
                  const float* __restrict__ mask, int H, int W,
                  int NXW, int NYS, int total_warps) {
    const float* __restrict__ src = src_is_scratch ? g_scratch : src_ext;
    float* __restrict__       dst = dst_is_scratch ? g_scratch : dst_ext;

    const int lane = threadIdx.x & 31;
    const int wu   = blockIdx.x * WPB + (threadIdx.x >> 5);
    if (wu >= total_warps) return;

    const int wc = wu % NXW;
    const int ys = (wu / NXW) % NYS;
    const int b  = wu / (NXW * NYS);

    const int x   = wc * WOUT2 + lane - 4;
    const int xc  = x < 0 ? 0 : (x >= W ? W - 1 : x);
    const bool in_x = (x >= 0) && (x < W);
    const bool store_lane = in_x && (lane >= 4) && (lane <= 27);
    const bool x_lo = (x == 0);
    const bool x_hi = (x == W - 1);

    const int y0 = ys * SH;
    const int y1 = min(y0 + SH, H);

    const int plane = H * W;
    const float* __restrict__ Tb  = src  + b * plane + xc;
    const float* __restrict__ ugb = ug   + b * plane + xc;
    const float* __restrict__ vgb = vg   + b * plane + xc;
    const float* __restrict__ mb  = mask + xc;
    float* __restrict__ dstb = dst + b * plane + x;

    const float inv_dy  = g_inv_dy;
    const float inv_2dy = g_inv_2dy;

    // ---- Rolling pipeline state ----
    float t_m1, t_0;                      // T rows r-1, r
    float hs1_m2 = 0.f, hs1_m1 = 0.f;     // horiz binomial of A1, rows r-2,r-1
    float T1a = 0.f, T1b = 0.f;           // T1 rows r-3, r-2
    float hs2_m2 = 0.f, hs2_m1 = 0.f;     // horiz binomial of A2, rows r-4,r-3
    float m1 = 0.f, m2 = 0.f, m3 = 0.f;   // mask rows r-1, r-2, r-3
    float ugd1 = 0.f, ugd2 = 0.f;         // ug rows r-1, r-2
    float vgd1 = 0.f, vgd2 = 0.f;
    float xd1  = 0.f, xd2  = 0.f;         // inv_2dx rows r-1, r-2

    const int r0 = y0 - 3;
    {
        int ya = r0 - 1; ya = ya < 0 ? 0 : ya;
        int yb = r0;     yb = yb < 0 ? 0 : yb;
        t_m1 = Tb[ya * W];
        t_0  = Tb[yb * W];
    }

    // One pipeline iteration at T-row r. Consumes loads for row r (+T row r+1),
    // stores output row r-3 when do_store.
    auto iterate = [&](int r, float t_p1, float ugn, float vgn, float mn,
                       float xin, bool do_store) {
        // ---- stage 1: advected field A1 at row r ----
        float a1 = 0.f;
        if (r >= 0 && r < H) {                         // warp-uniform
            float dTdy = (r == 0)     ? (t_p1 - t_0) * inv_dy
                       : (r == H - 1) ? (t_0 - t_m1) * inv_dy
                                      : (t_p1 - t_m1) * inv_2dy;
            float tl = __shfl_up_sync(0xffffffffu, t_0, 1);
            float tr = __shfl_down_sync(0xffffffffu, t_0, 1);
            float dTdx = x_lo ? (tr - t_0) * (2.0f * xin)
                       : x_hi ? (t_0 - tl) * (2.0f * xin)
                              : (tr - tl) * xin;
            a1 = fmaf(-DT_SEC * mn, fmaf(ugn, dTdx, vgn * dTdy), t_0);
            if (!in_x) a1 = 0.f;                       // zero pad at x edges
        }
        float al = __shfl_up_sync(0xffffffffu, a1, 1);
        float ar = __shfl_down_sync(0xffffffffu, a1, 1);
        float hs1_0 = al + 2.0f * a1 + ar;

        // T1 at row r-1 (vertical binomial * mask)
        float T1c = (hs1_m2 + 2.0f * hs1_m1 + hs1_0) * 0.0625f * m1;

        // ---- stage 2: advected field A2 at row r2 = r-2 (on T1) ----
        float a2 = 0.f;
        int r2 = r - 2;
        if (r2 >= 0 && r2 < H) {                       // warp-uniform
            float dTdy = (r2 == 0)     ? (T1c - T1b) * inv_dy
                       : (r2 == H - 1) ? (T1b - T1a) * inv_dy
                                       : (T1c - T1a) * inv_2dy;
            float tl = __shfl_up_sync(0xffffffffu, T1b, 1);
            float tr = __shfl_down_sync(0xffffffffu, T1b, 1);
            float dTdx = x_lo ? (tr - T1b) * (2.0f * xd2)
                       : x_hi ? (T1b - tl) * (2.0f * xd2)
                              : (tr - tl) * xd2;
            a2 = fmaf(-DT_SEC * m2, fmaf(ugd2, dTdx, vgd2 * dTdy), T1b);
            if (!in_x) a2 = 0.f;
        }
        float bl = __shfl_up_sync(0xffffffffu, a2, 1);
        float br = __shfl_down_sync(0xffffffffu, a2, 1);
        float hs2_0 = bl + 2.0f * a2 + br;

        // ---- output row o = r-3 ----
        if (do_store) {
            float v = (hs2_m2 + 2.0f * hs2_m1 + hs2_0) * 0.0625f * m3;
            if (store_lane) dstb[(r - 3) * W] = v;
        }

        // ---- shift rolling state ----
        t_m1 = t_0;   t_0 = t_p1;
        hs1_m2 = hs1_m1; hs1_m1 = hs1_0;
        T1a = T1b;    T1b = T1c;
        hs2_m2 = hs2_m1; hs2_m1 = hs2_0;
        m3 = m2; m2 = m1; m1 = mn;
        ugd2 = ugd1; ugd1 = ugn;
        vgd2 = vgd1; vgd1 = vgn;
        xd2 = xd1;  xd1 = xin;
    };

    // ---- warm-up: 6 iterations (r = y0-3 .. y0+2), batched loads, no store --
    {
        float tw[6], uw[6], vw[6], mw[6], xw[6];
        #pragma unroll
        for (int j = 0; j < 6; j++) {
            int r  = r0 + j;
            int rt = r + 1; rt = rt < 0 ? 0 : (rt >= H ? H - 1 : rt);
            int rc = r;     rc = rc < 0 ? 0 : (rc >= H ? H - 1 : rc);
            tw[j] = Tb[rt * W];
            uw[j] = ugb[rc * W];
            vw[j] = vgb[rc * W];
            mw[j] = mb[rc * W];
            xw[j] = g_inv_2dx[rc];
        }
        #pragma unroll
        for (int j = 0; j < 6; j++)
            iterate(r0 + j, tw[j], uw[j], vw[j], mw[j], xw[j], false);
    }

    // ---- main loop: r = y0+3 .. y1+2, chunks of 4, batched loads ----
    const int iters = y1 - y0;
    for (int k = 0; k < iters; k += 4) {
        float tb4[4], ub4[4], vb4[4], mb4[4], xb4[4];
        #pragma unroll
        for (int j = 0; j < 4; j++) {
            int r  = y0 + 3 + k + j;
            int rt = r + 1 >= H ? H - 1 : r + 1;
            int rc = r >= H ? H - 1 : r;
            tb4[j] = Tb[rt * W];
            ub4[j] = ugb[rc * W];
            vb4[j] = vgb[rc * W];
            mb4[j] = mb[rc * W];
            xb4[j] = g_inv_2dx[rc];
        }
        #pragma unroll
        for (int j = 0; j < 4; j++) {
            int idx = k + j;
            if (idx < iters)
                iterate(y0 + 3 + idx, tb4[j], ub4[j], vb4[j], mb4[j], xb4[j],
                        true);
        }
    }
}

extern "C" void kernel_launch(void* const* d_in, const int* in_sizes, int n_in,
                              void* d_out, int out_size) {
    const float* T    = (const float*)d_in[0];
    const float* ug   = (const float*)d_in[1];
    const float* vg   = (const float*)d_in[2];
    const float* lat  = (const float*)d_in[3];
    const float* lon  = (const float*)d_in[4];
    const float* mask = (const float*)d_in[5];
    float* out = (float*)d_out;

    const int H = in_sizes[3];
    const int W = in_sizes[4];
    const int B = in_sizes[0] / (H * W);

    setup_kernel<<<(H + 255) / 256, 256>>>(lat, lon, H);

    const int NXW = (W + WOUT2 - 1) / WOUT2;
    const int NYS = (H + SH - 1) / SH;
    const int total_warps = B * NYS * NXW;
    const int blocks = (total_warps + WPB - 1) / WPB;

    // 24 fused launches; ping-pong so the final one writes d_out.
    for (int p = 0; p < NPAIRS; p++) {
        int dst_is_out = ((NPAIRS - 1 - p) % 2) == 0;   // last pair -> out
        int src_is_scratch, dst_is_scratch;
        const float* src_ext;
        float* dst_ext;
        if (p == 0) { src_ext = T; src_is_scratch = 0; }
        else {
            int prev_dst_is_out = ((NPAIRS - p) % 2) == 0;
            if (prev_dst_is_out) { src_ext = out; src_is_scratch = 0; }
            else                 { src_ext = nullptr; src_is_scratch = 1; }
        }
        if (dst_is_out) { dst_ext = out; dst_is_scratch = 0; }
        else            { dst_ext = nullptr; dst_is_scratch = 1; }

        step2_kernel<<<blocks, 256>>>(src_ext, src_is_scratch,
                                      dst_ext, dst_is_scratch,
                                      ug, vg, mask, H, W,
                                      NXW, NYS, total_warps);
    }
}

// round 15
// speedup vs baseline: 1.2419x; 1.2419x over previous
#include <cuda_runtime.h>
#include <cuda_bf16.h>

#define R_EARTH  6371000.0f
#define DEG2RADF 0.017453292519943295f
#define DT_SEC   600.0f
#define NSTEPS   48
#define NPAIRS   (NSTEPS / 2)

#define WOUT2 24          // output columns per warp (32 lanes - 2*4 halo)
#define SH    128         // output rows per strip
#define WPB   8           // warps per block

// Static device buffers — NOT allocations.
__device__ __align__(16) float g_scratch[8u * 1024u * 1024u];  // T ping-pong
__device__ __align__(16) float g_P[8u * 1024u * 1024u];        // -DT*mask*ug*inv2dx
__device__ __align__(16) float g_Q[8u * 1024u * 1024u];        // -DT*mask*vg*inv2dy

__device__ float g_inv_2dx[4096];
__device__ float g_inv_2dy;

__global__ void setup_kernel(const float* __restrict__ lat,
                             const float* __restrict__ lon, int H) {
    float dlat = lat[1] - lat[0];
    float dlon = lon[1] - lon[0];
    float dy = R_EARTH * DEG2RADF * dlat;
    if (blockIdx.x == 0 && threadIdx.x == 0)
        g_inv_2dy = 0.5f / dy;
    float dx0 = R_EARTH * DEG2RADF * dlon;
    for (int i = blockIdx.x * blockDim.x + threadIdx.x; i < H;
         i += gridDim.x * blockDim.x) {
        float dx = dx0 * cosf(lat[i] * DEG2RADF);
        g_inv_2dx[i] = 0.5f / dx;
    }
}

// P/Q are step-invariant: fold -DT * mask * metric into the velocity fields.
__global__ void precompute_pq(const float* __restrict__ ug,
                              const float* __restrict__ vg,
                              const float* __restrict__ mask, int H, int W) {
    int p = blockIdx.x * blockDim.x + threadIdx.x;   // plane index
    int b = blockIdx.y;
    if (p >= H * W) return;
    int row = p / W;
    int idx = b * H * W + p;
    float s = -DT_SEC * mask[p];
    g_P[idx] = s * ug[idx] * g_inv_2dx[row];
    g_Q[idx] = s * vg[idx] * g_inv_2dy;
}

// TWO fused timesteps per launch; register-rolling y-sweep with prefetch
// double-buffering. Lane l covers x = wc*24 + l - 4 (halo 4 each side).
// Stage 1: T1 = step(T) in rolling registers; stage 2 (two rows behind):
// T2 = step(T1), stored. x-neighbors via shuffle, y via rolling registers.
__global__ __launch_bounds__(256, 3)
void step2_kernel(const float* __restrict__ src_ext, int src_is_scratch,
                  float* __restrict__ dst_ext, int dst_is_scratch,
                  const float* __restrict__ mask, int H, int W,
                  int NXW, int NYS, int total_warps) {
    const float* __restrict__ src = src_is_scratch ? g_scratch : src_ext;
    float* __restrict__       dst = dst_is_scratch ? g_scratch : dst_ext;

    const int lane = threadIdx.x & 31;
    const int wu   = blockIdx.x * WPB + (threadIdx.x >> 5);
    if (wu >= total_warps) return;

    const int wc = wu % NXW;
    const int ys = (wu / NXW) % NYS;
    const int b  = wu / (NXW * NYS);

    const int x   = wc * WOUT2 + lane - 4;
    const int xc  = x < 0 ? 0 : (x >= W ? W - 1 : x);
    const bool in_x = (x >= 0) && (x < W);
    const bool store_lane = in_x && (lane >= 4) && (lane <= 27);
    const bool x_lo = (x == 0);
    const bool x_hi = (x == W - 1);
    const float xfac = (x_lo || x_hi) ? 2.0f : 1.0f;  // one-sided dx factor

    const int y0 = ys * SH;
    const int y1 = min(y0 + SH, H);

    const int plane = H * W;
    const float* __restrict__ Tb = src + b * plane + xc;
    const float* __restrict__ Pb = g_P + b * plane + xc;
    const float* __restrict__ Qb = g_Q + b * plane + xc;
    const float* __restrict__ mb = mask + xc;
    float* __restrict__ dstb = dst + b * plane + x;

    // ---- Rolling pipeline state ----
    float t_m1, t_0;                      // T rows r-1, r
    float hs1_m2 = 0.f, hs1_m1 = 0.f;     // horiz binomial of A1, rows r-2,r-1
    float T1a = 0.f, T1b = 0.f;           // T1 rows r-3, r-2
    float hs2_m2 = 0.f, hs2_m1 = 0.f;     // horiz binomial of A2, rows r-4,r-3
    float m1 = 0.f, m2 = 0.f, m3 = 0.f;   // mask rows r-1, r-2, r-3
    float Pd1 = 0.f, Pd2 = 0.f;           // P rows r-1, r-2
    float Qd1 = 0.f, Qd2 = 0.f;           // Q rows r-1, r-2

    const int r0 = y0 - 3;
    {
        int ya = r0 - 1; ya = ya < 0 ? 0 : ya;
        int yb = r0;     yb = yb < 0 ? 0 : yb;
        t_m1 = Tb[ya * W];
        t_0  = Tb[yb * W];
    }

    auto iterate = [&](int r, float t_p1, float Pn, float Qn, float mn,
                       bool do_store) {
        // ---- stage 1: advected field A1 at row r ----
        float a1 = 0.f;
        if (r >= 0 && r < H) {                         // warp-uniform
            float tl = __shfl_up_sync(0xffffffffu, t_0, 1);
            float tr = __shfl_down_sync(0xffffffffu, t_0, 1);
            float xl = x_lo ? t_0 : tl;
            float xr = x_hi ? t_0 : tr;
            float yl = (r == 0)     ? t_0 : t_m1;      // uniform selects
            float yh = (r == H - 1) ? t_0 : t_p1;
            float Qe = (r == 0 || r == H - 1) ? 2.0f * Qn : Qn;
            a1 = fmaf(Pn, xr - xl, fmaf(Qe, yh - yl, t_0));
            a1 = in_x ? a1 : 0.f;                      // zero pad at x edges
        }
        float al = __shfl_up_sync(0xffffffffu, a1, 1);
        float ar = __shfl_down_sync(0xffffffffu, a1, 1);
        float hs1_0 = al + 2.0f * a1 + ar;

        // T1 at row r-1 (vertical binomial * mask)
        float T1c = (hs1_m2 + 2.0f * hs1_m1 + hs1_0) * 0.0625f * m1;

        // ---- stage 2: advected field A2 at row r2 = r-2 (on T1) ----
        float a2 = 0.f;
        int r2 = r - 2;
        if (r2 >= 0 && r2 < H) {                       // warp-uniform
            float tl = __shfl_up_sync(0xffffffffu, T1b, 1);
            float tr = __shfl_down_sync(0xffffffffu, T1b, 1);
            float xl = x_lo ? T1b : tl;
            float xr = x_hi ? T1b : tr;
            float yl = (r2 == 0)     ? T1b : T1a;
            float yh = (r2 == H - 1) ? T1b : T1c;
            float Qe = (r2 == 0 || r2 == H - 1) ? 2.0f * Qd2 : Qd2;
            a2 = fmaf(Pd2, xr - xl, fmaf(Qe, yh - yl, T1b));
            a2 = in_x ? a2 : 0.f;
        }
        float bl = __shfl_up_sync(0xffffffffu, a2, 1);
        float br = __shfl_down_sync(0xffffffffu, a2, 1);
        float hs2_0 = bl + 2.0f * a2 + br;

        // ---- output row o = r-3 ----
        if (do_store) {
            float v = (hs2_m2 + 2.0f * hs2_m1 + hs2_0) * 0.0625f * m3;
            if (store_lane) dstb[(r - 3) * W] = v;
        }

        // ---- shift rolling state ----
        t_m1 = t_0;   t_0 = t_p1;
        hs1_m2 = hs1_m1; hs1_m1 = hs1_0;
        T1a = T1b;    T1b = T1c;
        hs2_m2 = hs2_m1; hs2_m1 = hs2_0;
        m3 = m2; m2 = m1; m1 = mn;
        Pd2 = Pd1; Pd1 = Pn;
        Qd2 = Qd1; Qd1 = Qn;
    };

    // ---- warm-up: 6 iterations (r = y0-3 .. y0+2), batched, no store ----
    {
        float tw[6], pw[6], qw[6], mw[6];
        #pragma unroll
        for (int j = 0; j < 6; j++) {
            int r  = r0 + j;
            int rt = r + 1; rt = rt < 0 ? 0 : (rt >= H ? H - 1 : rt);
            int rc = r;     rc = rc < 0 ? 0 : (rc >= H ? H - 1 : rc);
            tw[j] = Tb[rt * W];
            pw[j] = xfac * Pb[rc * W];
            qw[j] = Qb[rc * W];
            mw[j] = mb[rc * W];
        }
        #pragma unroll
        for (int j = 0; j < 6; j++)
            iterate(r0 + j, tw[j], pw[j], qw[j], mw[j], false);
    }

    // ---- main loop: double-buffered prefetch, 4-row chunks ----
    const int iters = y1 - y0;            // SH (H % SH == 0 for this problem)

#define LOADC(kk, tA, pA, qA, mA)                                   \
    {                                                               \
        _Pragma("unroll")                                           \
        for (int j = 0; j < 4; j++) {                               \
            int r  = y0 + 3 + (kk) + j;                             \
            int rt = r + 1 >= H ? H - 1 : r + 1;                    \
            int rc = r     >= H ? H - 1 : r;                        \
            tA[j] = Tb[rt * W];                                     \
            pA[j] = xfac * Pb[rc * W];                              \
            qA[j] = Qb[rc * W];                                     \
            mA[j] = mb[rc * W];                                     \
        }                                                           \
    }
#define COMP4(kk, tA, pA, qA, mA)                                   \
    {                                                               \
        _Pragma("unroll")                                           \
        for (int j = 0; j < 4; j++)                                 \
            iterate(y0 + 3 + (kk) + j, tA[j], pA[j], qA[j], mA[j],  \
                    true);                                          \
    }

    float t0a[4], p0a[4], q0a[4], m0a[4];
    float t1a[4], p1a[4], q1a[4], m1a[4];

    LOADC(0, t0a, p0a, q0a, m0a);
    for (int k = 0; k < iters; k += 8) {
        LOADC(k + 4, t1a, p1a, q1a, m1a);
        COMP4(k, t0a, p0a, q0a, m0a);
        if (k + 8 < iters) LOADC(k + 8, t0a, p0a, q0a, m0a);
        COMP4(k + 4, t1a, p1a, q1a, m1a);
    }
#undef LOADC
#undef COMP4
}

extern "C" void kernel_launch(void* const* d_in, const int* in_sizes, int n_in,
                              void* d_out, int out_size) {
    const float* T    = (const float*)d_in[0];
    const float* ug   = (const float*)d_in[1];
    const float* vg   = (const float*)d_in[2];
    const float* lat  = (const float*)d_in[3];
    const float* lon  = (const float*)d_in[4];
    const float* mask = (const float*)d_in[5];
    float* out = (float*)d_out;

    const int H = in_sizes[3];
    const int W = in_sizes[4];
    const int B = in_sizes[0] / (H * W);

    setup_kernel<<<(H + 255) / 256, 256>>>(lat, lon, H);
    {
        dim3 g((H * W + 255) / 256, B);
        precompute_pq<<<g, 256>>>(ug, vg, mask, H, W);
    }

    const int NXW = (W + WOUT2 - 1) / WOUT2;
    const int NYS = (H + SH - 1) / SH;
    const int total_warps = B * NYS * NXW;
    const int blocks = (total_warps + WPB - 1) / WPB;

    // 24 fused launches; ping-pong so the final one writes d_out.
    for (int p = 0; p < NPAIRS; p++) {
        int dst_is_out = ((NPAIRS - 1 - p) % 2) == 0;   // last pair -> out
        int src_is_scratch, dst_is_scratch;
        const float* src_ext;
        float* dst_ext;
        if (p == 0) { src_ext = T; src_is_scratch = 0; }
        else {
            int prev_dst_is_out = ((NPAIRS - p) % 2) == 0;
            if (prev_dst_is_out) { src_ext = out; src_is_scratch = 0; }
            else                 { src_ext = nullptr; src_is_scratch = 1; }
        }
        if (dst_is_out) { dst_ext = out; dst_is_scratch = 0; }
        else            { dst_ext = nullptr; dst_is_scratch = 1; }

        step2_kernel<<<blocks, 256>>>(src_ext, src_is_scratch,
                                      dst_ext, dst_is_scratch,
                                      mask, H, W,
                                      NXW, NYS, total_warps);
    }
}

// round 16
// speedup vs baseline: 2.5142x; 2.0244x over previous
#include <cuda_runtime.h>
#include <cuda_bf16.h>

#define R_EARTH  6371000.0f
#define DEG2RADF 0.017453292519943295f
#define DT_SEC   600.0f
#define NSTEPS   48
#define NPAIRS   (NSTEPS / 2)

#define WOUT2 56          // output columns per warp (32 lanes * 2 - 2*4 halo)
#define SH    64          // output rows per strip
#define WPB   8           // warps per block

// Static device buffers — NOT allocations.
__device__ __align__(16) float g_scratch[8u * 1024u * 1024u];  // T ping-pong
__device__ __align__(16) float g_P[8u * 1024u * 1024u];        // -DT*mask*ug*inv2dx
__device__ __align__(16) float g_Q[8u * 1024u * 1024u];        // -DT*mask*vg*inv2dy

__device__ float g_inv_2dx[4096];
__device__ float g_inv_2dy;

__global__ void setup_kernel(const float* __restrict__ lat,
                             const float* __restrict__ lon, int H) {
    float dlat = lat[1] - lat[0];
    float dlon = lon[1] - lon[0];
    float dy = R_EARTH * DEG2RADF * dlat;
    if (blockIdx.x == 0 && threadIdx.x == 0)
        g_inv_2dy = 0.5f / dy;
    float dx0 = R_EARTH * DEG2RADF * dlon;
    for (int i = blockIdx.x * blockDim.x + threadIdx.x; i < H;
         i += gridDim.x * blockDim.x) {
        float dx = dx0 * cosf(lat[i] * DEG2RADF);
        g_inv_2dx[i] = 0.5f / dx;
    }
}

// P/Q are step-invariant: fold -DT * mask * metric into the velocity fields.
__global__ void precompute_pq(const float* __restrict__ ug,
                              const float* __restrict__ vg,
                              const float* __restrict__ mask, int H, int W) {
    int p = blockIdx.x * blockDim.x + threadIdx.x;   // plane index
    int b = blockIdx.y;
    if (p >= H * W) return;
    int row = p / W;
    int idx = b * H * W + p;
    float s = -DT_SEC * mask[p];
    g_P[idx] = s * ug[idx] * g_inv_2dx[row];
    g_Q[idx] = s * vg[idx] * g_inv_2dy;
}

// TWO fused timesteps per launch; register-rolling y-sweep, float2 per lane.
// Lane l carries columns x, x+1 with x = wc*56 + 2*l - 4 (2-lane halo/side).
// Stage 1: T1 = step(T) in rolling registers; stage 2 (two rows behind):
// T2 = step(T1), stored. x-neighbors: in-register + 2 shuffles per exchange.
__global__ __launch_bounds__(256, 2)
void step2_kernel(const float* __restrict__ src_ext, int src_is_scratch,
                  float* __restrict__ dst_ext, int dst_is_scratch,
                  const float* __restrict__ mask, int H, int W,
                  int NXW, int NYS, int total_warps) {
    const float* __restrict__ src = src_is_scratch ? g_scratch : src_ext;
    float* __restrict__       dst = dst_is_scratch ? g_scratch : dst_ext;

    const int lane = threadIdx.x & 31;
    const int wu   = blockIdx.x * WPB + (threadIdx.x >> 5);
    if (wu >= total_warps) return;

    const int wc = wu % NXW;
    const int ys = (wu / NXW) % NYS;
    const int b  = wu / (NXW * NYS);

    const int x  = wc * WOUT2 + 2 * lane - 4;        // even; pair (x, x+1)
    int xp = x < 0 ? 0 : (x > W - 2 ? W - 2 : x);    // clamped, even
    const bool in_x = (x >= 0) && (x < W);           // whole pair in domain
    const bool store_lane = in_x && (lane >= 2) && (lane <= 29);
    const bool x_lo  = (x == 0);
    const bool x_hi1 = (x + 1 == W - 1);
    const float xf_lo = x_lo  ? 2.0f : 1.0f;         // one-sided dx factors
    const float xf_hi = x_hi1 ? 2.0f : 1.0f;

    const int y0 = ys * SH;
    const int y1 = min(y0 + SH, H);

    const int plane = H * W;
    const float* __restrict__ Tb = src + b * plane + xp;
    const float* __restrict__ Pb = g_P + b * plane + xp;
    const float* __restrict__ Qb = g_Q + b * plane + xp;
    const float* __restrict__ mb = mask + xp;
    float* __restrict__ dstb = dst + b * plane + xp;

    // ---- Rolling pipeline state (float2 = column pair) ----
    float2 t_m1, t_0;                                  // T rows r-1, r
    float2 hs1_m2 = {0.f,0.f}, hs1_m1 = {0.f,0.f};     // hbinom(A1) r-2, r-1
    float2 T1a = {0.f,0.f}, T1b = {0.f,0.f};           // T1 rows r-3, r-2
    float2 hs2_m2 = {0.f,0.f}, hs2_m1 = {0.f,0.f};     // hbinom(A2) r-4, r-3
    float2 m1 = {0.f,0.f}, m2 = {0.f,0.f}, m3 = {0.f,0.f};
    float2 Pd1 = {0.f,0.f}, Pd2 = {0.f,0.f};
    float2 Qd1 = {0.f,0.f}, Qd2 = {0.f,0.f};

    const int r0 = y0 - 3;
    {
        int ya = r0 - 1; ya = ya < 0 ? 0 : ya;
        int yb = r0;     yb = yb < 0 ? 0 : yb;
        t_m1 = *(const float2*)(Tb + ya * W);
        t_0  = *(const float2*)(Tb + yb * W);
    }

    auto iterate = [&](int r, float2 t_p1, float2 Pn, float2 Qn, float2 mn,
                       bool do_store) {
        // ---- stage 1: advected field A1 at row r ----
        float2 a1 = {0.f, 0.f};
        if (r >= 0 && r < H) {                         // warp-uniform
            float tl_hi = __shfl_up_sync(0xffffffffu, t_0.y, 1);
            float tr_lo = __shfl_down_sync(0xffffffffu, t_0.x, 1);
            float xl_lo = x_lo  ? t_0.x : tl_hi;
            float xr_hi = x_hi1 ? t_0.y : tr_lo;
            float Qs = (r == 0 || r == H - 1) ? 2.0f : 1.0f;
            float2 yl, yh;
            yl = (r == 0)     ? t_0 : t_m1;
            yh = (r == H - 1) ? t_0 : t_p1;
            a1.x = fmaf(Pn.x, t_0.y - xl_lo,
                        fmaf(Qs * Qn.x, yh.x - yl.x, t_0.x));
            a1.y = fmaf(Pn.y, xr_hi - t_0.x,
                        fmaf(Qs * Qn.y, yh.y - yl.y, t_0.y));
            if (!in_x) { a1.x = 0.f; a1.y = 0.f; }     // zero pad at x edges
        }
        float au = __shfl_up_sync(0xffffffffu, a1.y, 1);
        float ad = __shfl_down_sync(0xffffffffu, a1.x, 1);
        float2 hs1_0;
        hs1_0.x = au   + 2.0f * a1.x + a1.y;
        hs1_0.y = a1.x + 2.0f * a1.y + ad;

        // T1 at row r-1 (vertical binomial * mask)
        float2 T1c;
        T1c.x = (hs1_m2.x + 2.0f * hs1_m1.x + hs1_0.x) * 0.0625f * m1.x;
        T1c.y = (hs1_m2.y + 2.0f * hs1_m1.y + hs1_0.y) * 0.0625f * m1.y;

        // ---- stage 2: advected field A2 at row r2 = r-2 (on T1) ----
        float2 a2 = {0.f, 0.f};
        int r2 = r - 2;
        if (r2 >= 0 && r2 < H) {                       // warp-uniform
            float tl_hi = __shfl_up_sync(0xffffffffu, T1b.y, 1);
            float tr_lo = __shfl_down_sync(0xffffffffu, T1b.x, 1);
            float xl_lo = x_lo  ? T1b.x : tl_hi;
            float xr_hi = x_hi1 ? T1b.y : tr_lo;
            float Qs = (r2 == 0 || r2 == H - 1) ? 2.0f : 1.0f;
            float2 yl, yh;
            yl = (r2 == 0)     ? T1b : T1a;
            yh = (r2 == H - 1) ? T1b : T1c;
            a2.x = fmaf(Pd2.x, T1b.y - xl_lo,
                        fmaf(Qs * Qd2.x, yh.x - yl.x, T1b.x));
            a2.y = fmaf(Pd2.y, xr_hi - T1b.x,
                        fmaf(Qs * Qd2.y, yh.y - yl.y, T1b.y));
            if (!in_x) { a2.x = 0.f; a2.y = 0.f; }
        }
        float bu = __shfl_up_sync(0xffffffffu, a2.y, 1);
        float bd = __shfl_down_sync(0xffffffffu, a2.x, 1);
        float2 hs2_0;
        hs2_0.x = bu   + 2.0f * a2.x + a2.y;
        hs2_0.y = a2.x + 2.0f * a2.y + bd;

        // ---- output row o = r-3 ----
        if (do_store && store_lane) {
            float2 v;
            v.x = (hs2_m2.x + 2.0f * hs2_m1.x + hs2_0.x) * 0.0625f * m3.x;
            v.y = (hs2_m2.y + 2.0f * hs2_m1.y + hs2_0.y) * 0.0625f * m3.y;
            *(float2*)(dstb + (r - 3) * W) = v;
        }

        // ---- shift rolling state ----
        t_m1 = t_0;   t_0 = t_p1;
        hs1_m2 = hs1_m1; hs1_m1 = hs1_0;
        T1a = T1b;    T1b = T1c;
        hs2_m2 = hs2_m1; hs2_m1 = hs2_0;
        m3 = m2; m2 = m1; m1 = mn;
        Pd2 = Pd1; Pd1 = Pn;
        Qd2 = Qd1; Qd1 = Qn;
    };

    // ---- warm-up: 6 iterations (r = y0-3 .. y0+2), batched, no store ----
    {
        float2 tw[6], pw[6], qw[6], mw[6];
        #pragma unroll
        for (int j = 0; j < 6; j++) {
            int r  = r0 + j;
            int rt = r + 1; rt = rt < 0 ? 0 : (rt >= H ? H - 1 : rt);
            int rc = r;     rc = rc < 0 ? 0 : (rc >= H ? H - 1 : rc);
            tw[j] = *(const float2*)(Tb + rt * W);
            pw[j] = *(const float2*)(Pb + rc * W);
            pw[j].x *= xf_lo;  pw[j].y *= xf_hi;
            qw[j] = *(const float2*)(Qb + rc * W);
            mw[j] = *(const float2*)(mb + rc * W);
        }
        #pragma unroll
        for (int j = 0; j < 6; j++)
            iterate(r0 + j, tw[j], pw[j], qw[j], mw[j], false);
    }

    // ---- main loop: 4-row chunks, batched loads (16 LDG.64 in flight) ----
    const int iters = y1 - y0;                         // SH (H % SH == 0)
    for (int k = 0; k < iters; k += 4) {
        float2 tA[4], pA[4], qA[4], mA[4];
        #pragma unroll
        for (int j = 0; j < 4; j++) {
            int r  = y0 + 3 + k + j;
            int rt = r + 1 >= H ? H - 1 : r + 1;
            int rc = r     >= H ? H - 1 : r;
            tA[j] = *(const float2*)(Tb + rt * W);
            pA[j] = *(const float2*)(Pb + rc * W);
            pA[j].x *= xf_lo;  pA[j].y *= xf_hi;
            qA[j] = *(const float2*)(Qb + rc * W);
            mA[j] = *(const float2*)(mb + rc * W);
        }
        #pragma unroll
        for (int j = 0; j < 4; j++)
            iterate(y0 + 3 + k + j, tA[j], pA[j], qA[j], mA[j], true);
    }
}

extern "C" void kernel_launch(void* const* d_in, const int* in_sizes, int n_in,
                              void* d_out, int out_size) {
    const float* T    = (const float*)d_in[0];
    const float* ug   = (const float*)d_in[1];
    const float* vg   = (const float*)d_in[2];
    const float* lat  = (const float*)d_in[3];
    const float* lon  = (const float*)d_in[4];
    const float* mask = (const float*)d_in[5];
    float* out = (float*)d_out;

    const int H = in_sizes[3];
    const int W = in_sizes[4];
    const int B = in_sizes[0] / (H * W);

    setup_kernel<<<(H + 255) / 256, 256>>>(lat, lon, H);
    {
        dim3 g((H * W + 255) / 256, B);
        precompute_pq<<<g, 256>>>(ug, vg, mask, H, W);
    }

    const int NXW = (W + WOUT2 - 1) / WOUT2;
    const int NYS = (H + SH - 1) / SH;
    const int total_warps = B * NYS * NXW;
    const int blocks = (total_warps + WPB - 1) / WPB;

    // 24 fused launches; ping-pong so the final one writes d_out.
    for (int p = 0; p < NPAIRS; p++) {
        int dst_is_out = ((NPAIRS - 1 - p) % 2) == 0;   // last pair -> out
        int src_is_scratch, dst_is_scratch;
        const float* src_ext;
        float* dst_ext;
        if (p == 0) { src_ext = T; src_is_scratch = 0; }
        else {
            int prev_dst_is_out = ((NPAIRS - p) % 2) == 0;
            if (prev_dst_is_out) { src_ext = out; src_is_scratch = 0; }
            else                 { src_ext = nullptr; src_is_scratch = 1; }
        }
        if (dst_is_out) { dst_ext = out; dst_is_scratch = 0; }
        else            { dst_ext = nullptr; dst_is_scratch = 1; }

        step2_kernel<<<blocks, 256>>>(src_ext, src_is_scratch,
                                      dst_ext, dst_is_scratch,
                                      mask, H, W,
                                      NXW, NYS, total_warps);
    }
}